// round 12
// baseline (speedup 1.0000x reference)
#include <cuda_runtime.h>
#include <math.h>

#define Nn 4096
#define Ee 8192
#define Mm 128
#define ND 128
#define ED 64
#define PQ 16
#define NP (Nn*PQ)
#define LAYERS 4
#define TAU 0.25f
#define FRIC 0.1f
#define MAXD 32
#define NB 128
#define BT 256
#define NT (NB*BT)     // 32768 threads
#define NWP (NT/32)    // 1024 warps
#define DYN_SMEM (MAXD*BT*6)   // s_w 32KB + s_o 16KB

// ---------------- device scratch (no allocation allowed) ----------------
__device__ float g_a[Nn], g_c[Nn], g_avt[Nn], g_avu[Nn];
__device__ float g_pd0[Nn], g_pwu[Nn], g_pn[Nn], g_qd0[Nn], g_Wn[Nn];
__device__ int   g_mol[Nn];
__device__ int   g_cnt[Nn];            // zero at launch entry; reset at end
__device__ int   g_adjT[MAXD * Nn];    // [slot][node] -> other-node id (coalesced)
__device__ float g_wincT[MAXD * Nn];   // [slot][node] -> edge weight
__device__ int   g_slotU[Ee], g_slotV[Ee];
__device__ float g_p0[NP], g_q0[NP];
__device__ float2 g_scA[Nn], g_scB[Nn];   // packed (su, cumSt)
__device__ float g_Gm[LAYERS*Mm], g_Sm[LAYERS*Mm], g_h[Mm], g_d[Mm], g_S[LAYERS];
__device__ unsigned g_bar;             // monotonic grid-barrier counter

__device__ __forceinline__ float warp_sum(float v) {
#pragma unroll
    for (int o = 16; o; o >>= 1) v += __shfl_xor_sync(0xffffffffu, v, o);
    return v;
}
__device__ __forceinline__ float sigmoidf(float x) { return 1.f / (1.f + expf(-x)); }
__device__ __forceinline__ float fsigmoid(float x) { return 1.f / (1.f + __expf(-x)); }
__device__ __forceinline__ float fsoftplus(float x) { return fmaxf(x, 0.f) + __logf(1.f + __expf(-fabsf(x))); }

// grid barrier across NB blocks; monotonic counter, no reset needed
// (each launch consumes exactly 8*NB increments; invariant % NB == 0).
__device__ __forceinline__ void gsync() {
    __threadfence();
    __syncthreads();
    if (threadIdx.x == 0) {
        unsigned t = atomicAdd(&g_bar, 1u);
        unsigned target = (t / NB + 1u) * NB;
        while (*((volatile unsigned*)&g_bar) < target) __nanosleep(32);
    }
    __syncthreads();
    __threadfence();
}

// ======== the whole pipeline in ONE kernel ========
__global__ void __launch_bounds__(BT, 1)
kAll(const float* __restrict__ vf, const float* __restrict__ ef,
     const int* __restrict__ us, const int* __restrict__ vs,
     const float* __restrict__ mnm,
     const float* __restrict__ We, const float* __restrict__ be,
     const float* __restrict__ Wp, const float* __restrict__ bp,
     const float* __restrict__ Wq, const float* __restrict__ bq,
     const float* __restrict__ Wt, const float* __restrict__ Wu,
     float* __restrict__ out)
{
    extern __shared__ char smraw[];
    float*          s_w = (float*)smraw;                 // [MAXD][BT]
    unsigned short* s_o = (unsigned short*)(s_w + MAXD*BT);
    __shared__ float sh[8];
    __shared__ float shPN;

    const int t    = threadIdx.x;
    const int tid  = blockIdx.x * BT + t;
    const int lane = t & 31;
    const int gw   = tid >> 5;            // global warp id, 0..1023

    float nWt = 0.f, nWu = 0.f, dTU = 0.f;
#pragma unroll
    for (int k = 0; k < PQ; k++) {
        float a = Wu[ND+k], b = Wt[ND+k];
        nWu += a*a; nWt += b*b; dTU += a*b;
    }

    // ================= Phase A (= k1) =================
    if (tid < Nn) g_Wn[tid] = 0.f;
    if (tid < LAYERS*Mm) { g_Gm[tid] = 0.f; g_Sm[tid] = 0.f; }
    if (tid < Mm) { g_h[tid] = 0.f; g_d[tid] = 0.f; }
    if (tid < LAYERS) g_S[tid] = 0.f;

    for (int idx = tid; idx < Mm * Nn; idx += NT)
        if (mnm[idx] > 0.5f) g_mol[idx & (Nn - 1)] = idx >> 12;

    for (int e = tid; e < Ee; e += NT) {
        int u = us[e], v = vs[e];
        int s1 = atomicAdd(&g_cnt[u], 1);
        if (s1 < MAXD) g_adjT[s1 * Nn + u] = v;
        g_slotU[e] = s1;
        if (u != v) {
            int s2 = atomicAdd(&g_cnt[v], 1);
            if (s2 < MAXD) g_adjT[s2 * Nn + v] = u;
            g_slotV[e] = s2;
        }
    }

    for (int n = gw; n < Nn; n += NWP) {
        float v0 = vf[n*ND+lane], v1 = vf[n*ND+lane+32], v2 = vf[n*ND+lane+64], v3 = vf[n*ND+lane+96];
        float sa = warp_sum(v0*We[lane]     + v1*We[lane+32]     + v2*We[lane+64]     + v3*We[lane+96]);
        float sc = warp_sum(v0*We[192+lane] + v1*We[192+lane+32] + v2*We[192+lane+64] + v3*We[192+lane+96]);
        float st = warp_sum(v0*Wt[lane]     + v1*Wt[lane+32]     + v2*Wt[lane+64]     + v3*Wt[lane+96]);
        float su = warp_sum(v0*Wu[lane]     + v1*Wu[lane+32]     + v2*Wu[lane+64]     + v3*Wu[lane+96]);
        float pk = 0.f;
#pragma unroll
        for (int k = 0; k < PQ; k++) {
            float s = warp_sum(v0*Wp[lane*PQ+k] + v1*Wp[(lane+32)*PQ+k] +
                               v2*Wp[(lane+64)*PQ+k] + v3*Wp[(lane+96)*PQ+k]);
            if (lane == k) pk = tanhf(s + bp[k]);
        }
        float pd0 = warp_sum(lane < PQ ? pk * Wt[ND+lane] : 0.f);
        float pwu = warp_sum(lane < PQ ? pk * Wu[ND+lane] : 0.f);
        float pn  = warp_sum(lane < PQ ? pk * pk          : 0.f);
        if (lane < PQ) g_p0[n*PQ+lane] = pk;
        if (lane == 0) {
            g_a[n] = sa; g_c[n] = sc; g_avt[n] = st; g_avu[n] = su;
            g_pd0[n] = pd0; g_pwu[n] = pwu; g_pn[n] = pn;
        }
    }
    gsync();  // 1

    // ================= Phase B (= k2) =================
    for (int e = gw; e < Ee; e += NWP) {
        float s = ef[e*ED+lane] * We[128+lane] + ef[e*ED+32+lane] * We[160+lane];
        s = warp_sum(s);
        if (lane == 0) {
            int u = us[e], v = vs[e];
            float w = sigmoidf(g_a[u] + g_c[v] + s + be[0]);
            int s1 = g_slotU[e];
            if (s1 < MAXD) g_wincT[s1 * Nn + u] = w;
            if (u != v) {
                int s2 = g_slotV[e];
                if (s2 < MAXD) g_wincT[s2 * Nn + v] = w;
                atomicAdd(&g_Wn[u], w);
                atomicAdd(&g_Wn[v], w);
            }
        }
    }
    gsync();  // 2

    // ================= Phase C (= k3) =================
    for (int n = gw; n < Nn; n += NWP) {
        float x0 = vf[n*ND+lane], x1 = vf[n*ND+lane+32], x2 = vf[n*ND+lane+64], x3 = vf[n*ND+lane+96];
        float Wn = g_Wn[n];
        float e0 = Wn*x0, e1 = Wn*x1, e2 = Wn*x2, e3 = Wn*x3;
        int dg = min(g_cnt[n], MAXD);
        for (int j = 0; j < dg; j++) {
            int   o = g_adjT[j*Nn + n];
            float w = g_wincT[j*Nn + n];
            e0 += w * vf[o*ND+lane];
            e1 += w * vf[o*ND+lane+32];
            e2 += w * vf[o*ND+lane+64];
            e3 += w * vf[o*ND+lane+96];
        }
        float qk = 0.f;
#pragma unroll
        for (int k = 0; k < PQ; k++) {
            float s = warp_sum(e0*Wq[lane*PQ+k] + e1*Wq[(lane+32)*PQ+k] +
                               e2*Wq[(lane+64)*PQ+k] + e3*Wq[(lane+96)*PQ+k]);
            if (lane == k) qk = tanhf(s + bq[k]);
        }
        float qd0 = warp_sum(lane < PQ ? qk * Wu[ND+lane] : 0.f);
        if (lane < PQ) g_q0[n*PQ+lane] = qk;
        if (lane == 0) g_qd0[n] = qd0;
    }
    gsync();  // 3

    // ================= P0..P4 (= kBig; nodes on blocks 0..15) =================
    const int  n4     = tid;            // thread-per-node for blocks < 16
    const bool active = (n4 < Nn);
    int deg = 0, mol = 0;
    float Wn = 0.f, pd0 = 0.f, pwu = 0.f, zub = 0.f, atp = 0.f;
    float su = 0.f, cum = 0.f, wS = 0.f, wG = 0.f, cumG = 0.f;

    if (active) {
        deg = min(g_cnt[n4], MAXD);
        mol = g_mol[n4];
        Wn  = g_Wn[n4];
        pd0 = g_pd0[n4]; pwu = g_pwu[n4];
        for (int j = 0; j < deg; j++) {
            s_o[j*BT + t] = (unsigned short)g_adjT[j*Nn + n4];
            s_w[j*BT + t] = g_wincT[j*Nn + n4];
        }
        float s = Wn * g_qd0[n4];
        for (int j = 0; j < deg; j++)
            s += s_w[j*BT + t] * g_qd0[s_o[j*BT + t]];
        zub = g_avu[n4] + s;
        atp = g_avt[n4] + pd0;

        float st = fsigmoid(atp);
        su = fsigmoid(zub);
        cum = st;
        g_scA[n4] = make_float2(su, cum);
        wS = 4.f * st;
        atomicAdd(&g_Sm[mol], st);
        float sl = st*st*nWt - 2.f*st*pd0;
        sl = warp_sum(sl);
        if (lane == 0) atomicAdd(&g_S[0], sl);
    }
    gsync();  // 4

    for (int ph = 1; ph <= 4; ph++) {
        if (active) {
            const float2* IN  = (ph & 1) ? g_scA : g_scB;
            float2*       OUT = (ph & 1) ? g_scB : g_scA;

            float gg = Wn * su, G = Wn * cum;
            for (int j = 0; j < deg; j++) {
                float  w  = s_w[j*BT + t];
                float2 sc = IN[s_o[j*BT + t]];
                gg += w * sc.x;
                G  += w * sc.y;
            }
            atomicAdd(&g_Gm[(ph-1)*Mm + mol], gg);
            cumG += gg;
            wG += (float)((ph == 1) ? 4 : (5 - ph)) * gg;

            if (ph < 4) {
                float zt = atp - TAU * (dTU * cumG + FRIC * nWt * cum);
                float stn = fsigmoid(zt);
                float zu = zub + TAU * dTU * G;
                float sun = fsigmoid(zu);
                float cumn = cum + stn;
                OUT[n4] = make_float2(sun, cumn);
                wS += (float)(4 - ph) * stn;
                atomicAdd(&g_Sm[ph*Mm + mol], stn);
                float alpha = stn + TAU * FRIC * cum;
                float beta  = TAU * cumG;
                float sl = alpha*alpha*nWt + beta*beta*nWu + 2.f*alpha*beta*dTU
                         - 2.f*alpha*pd0 - 2.f*beta*pwu;
                sl = warp_sum(sl);
                if (lane == 0) atomicAdd(&g_S[ph], sl);
                if (ph == 3) {   // zt/zu/stn are layer-4 values
                    atomicAdd(&g_h[mol], fsoftplus(zt) + fsoftplus(zu));
                    atomicAdd(&g_d[mol], stn * stn);
                }
                su = sun; cum = cumn;
            }
        }
        gsync();  // 5..8
    }

    // ================= outputs =================
    if (active) {
        float cp1 = -(TAU*FRIC) * wS, cp2 = -TAU * wG, cq = TAU * wS;
#pragma unroll
        for (int k = 0; k < PQ; k++) {
            out[n4*PQ + k]      = 0.2f * (5.f*g_p0[n4*PQ+k] + cp1*Wt[ND+k] + cp2*Wu[ND+k]);
            out[NP + n4*PQ + k] = 0.2f * (5.f*g_q0[n4*PQ+k] + cq*Wt[ND+k]);
        }
        g_cnt[n4] = 0;
    }

    // ---- block 0: scalars + h/d ----
    if (blockIdx.x == 0) {
        float pn = 0.f;
        for (int i = t; i < Nn; i += BT) pn += g_pn[i];
        pn = warp_sum(pn);
        if (lane == 0) sh[t >> 5] = pn;
        __syncthreads();
        if (t == 0) {
            float s0 = 0.f;
            for (int i = 0; i < 8; i++) s0 += sh[i];
            shPN = s0;
        }
        __syncthreads();
        if (t < 32) {
            float cT = 0.f;
            for (int i = 0; i < LAYERS; i++) {
                float term = 0.f;
                for (int m = lane; m < Mm; m += 32) {
                    float Gm = g_Gm[i*Mm+m], Sm = g_Sm[i*Mm+m];
                    term += Gm*Gm*nWu + 2.f*FRIC*Gm*Sm*dTU + FRIC*FRIC*Sm*Sm*nWt;
                }
                term = warp_sum(term);
                cT += TAU * sqrtf(term);
            }
            if (lane == 0) {
                float sT = 0.f;
                for (int i = 0; i < LAYERS; i++) sT += sqrtf(g_S[i] + shPN);
                out[2*NP + 0] = sT;
                out[2*NP + 1] = cT;
            }
        }
        if (t < Mm) {
            out[2*NP + 2 + t]      = g_h[t];
            out[2*NP + 2 + Mm + t] = g_d[t] * nWt;
        }
    }
}

extern "C" void kernel_launch(void* const* d_in, const int* in_sizes, int n_in,
                              void* d_out, int out_size)
{
    const float* vf  = (const float*)d_in[0];
    const float* ef  = (const float*)d_in[1];
    const int*   us  = (const int*)  d_in[2];
    const int*   vs  = (const int*)  d_in[3];
    const float* mnm = (const float*)d_in[4];
    const float* We  = (const float*)d_in[8];
    const float* be  = (const float*)d_in[9];
    const float* Wp  = (const float*)d_in[10];
    const float* bp  = (const float*)d_in[11];
    const float* Wq  = (const float*)d_in[12];
    const float* bq  = (const float*)d_in[13];
    const float* Wt  = (const float*)d_in[14];
    const float* Wu  = (const float*)d_in[15];
    float* out = (float*)d_out;

    cudaFuncSetAttribute(kAll, cudaFuncAttributeMaxDynamicSharedMemorySize, DYN_SMEM);
    kAll<<<NB, BT, DYN_SMEM>>>(vf, ef, us, vs, mnm, We, be, Wp, bp, Wq, bq, Wt, Wu, out);
}

// round 13
// speedup vs baseline: 1.0753x; 1.0753x over previous
#include <cuda_runtime.h>
#include <math.h>

#define Nn 4096
#define Ee 8192
#define Mm 128
#define ND 128
#define ED 64
#define PQ 16
#define NP (Nn*PQ)
#define LAYERS 4
#define TAU 0.25f
#define FRIC 0.1f
#define MAXD 32
#define GB_NB 16
#define GB_BT 256
#define DYN_SMEM (MAXD*GB_BT*6)   // s_w 32KB + s_o 16KB

// ---------------- device scratch (no allocation allowed) ----------------
__device__ float g_a[Nn], g_c[Nn], g_avt[Nn], g_avu[Nn];
__device__ float g_pd0[Nn], g_pwu[Nn], g_pn[Nn], g_qd0[Nn], g_Wn[Nn];
__device__ int   g_mol[Nn];
__device__ int   g_cnt[Nn];            // zero at k1 entry; reset in kBig
__device__ int   g_adjT[MAXD * Nn];    // [slot][node] -> other-node id (coalesced)
__device__ float g_wincT[MAXD * Nn];   // [slot][node] -> edge weight
__device__ int   g_slotU[Ee], g_slotV[Ee];
__device__ float g_se[Ee];             // hoisted ef-dot per edge
__device__ float g_p0[NP], g_q0[NP];
__device__ float2 g_scA[Nn], g_scB[Nn];   // packed (su, cumSt)
__device__ float g_Gm[LAYERS*Mm], g_Sm[LAYERS*Mm], g_h[Mm], g_d[Mm], g_S[LAYERS];
__device__ unsigned g_bar;             // monotonic grid-barrier counter

__device__ __forceinline__ float warp_sum(float v) {
#pragma unroll
    for (int o = 16; o; o >>= 1) v += __shfl_xor_sync(0xffffffffu, v, o);
    return v;
}
__device__ __forceinline__ float fsigmoid(float x) { return 1.f / (1.f + __expf(-x)); }
__device__ __forceinline__ float ftanh(float x)    { return 2.f / (1.f + __expf(-2.f*x)) - 1.f; }
__device__ __forceinline__ float fsoftplus(float x) { return fmaxf(x, 0.f) + __logf(1.f + __expf(-fabsf(x))); }

// grid barrier across GB_NB blocks; monotonic counter, no reset needed
// (each launch consumes exactly 5*GB_NB increments; invariant % GB_NB == 0).
__device__ __forceinline__ void gsync() {
    __threadfence();
    __syncthreads();
    if (threadIdx.x == 0) {
        unsigned t = atomicAdd(&g_bar, 1u);
        unsigned target = (t / GB_NB + 1u) * GB_NB;
        while (*((volatile unsigned*)&g_bar) < target) __nanosleep(32);
    }
    __syncthreads();
    __threadfence();
}

// ======== k1: node setup + mol ids + adjacency + ef-dot (hoisted from k2) ========
__global__ void k1(const float* __restrict__ vf, const float* __restrict__ ef,
                   const float* __restrict__ mnm,
                   const int* __restrict__ us, const int* __restrict__ vs,
                   const float* __restrict__ We, const float* __restrict__ Wp,
                   const float* __restrict__ bp, const float* __restrict__ Wt,
                   const float* __restrict__ Wu)
{
    int tid  = blockIdx.x * blockDim.x + threadIdx.x;   // 131072 threads
    int lane = threadIdx.x & 31;
    int n    = tid >> 5;                                 // warp -> node (4096 warps)

    if (tid < Nn) g_Wn[tid] = 0.f;
    if (tid < LAYERS*Mm) { g_Gm[tid] = 0.f; g_Sm[tid] = 0.f; }
    if (tid < Mm) { g_h[tid] = 0.f; g_d[tid] = 0.f; }
    if (tid < LAYERS) g_S[tid] = 0.f;

    for (int idx = tid; idx < Mm * Nn; idx += 131072)
        if (mnm[idx] > 0.5f) g_mol[idx & (Nn - 1)] = idx >> 12;

    for (int e = tid; e < Ee; e += 131072) {
        int u = us[e], v = vs[e];
        int s1 = atomicAdd(&g_cnt[u], 1);
        if (s1 < MAXD) g_adjT[s1 * Nn + u] = v;
        g_slotU[e] = s1;
        if (u != v) {
            int s2 = atomicAdd(&g_cnt[v], 1);
            if (s2 < MAXD) g_adjT[s2 * Nn + v] = u;
            g_slotV[e] = s2;
        }
    }

    // hoisted ef-dot: independent of node results (warp per edge, 2 edges/warp)
    for (int e = n; e < Ee; e += 4096) {
        float s = ef[e*ED+lane] * We[128+lane] + ef[e*ED+32+lane] * We[160+lane];
        s = warp_sum(s);
        if (lane == 0) g_se[e] = s;
    }

    float v0 = vf[n*ND+lane], v1 = vf[n*ND+lane+32], v2 = vf[n*ND+lane+64], v3 = vf[n*ND+lane+96];
    float sa = warp_sum(v0*We[lane]     + v1*We[lane+32]     + v2*We[lane+64]     + v3*We[lane+96]);
    float sc = warp_sum(v0*We[192+lane] + v1*We[192+lane+32] + v2*We[192+lane+64] + v3*We[192+lane+96]);
    float st = warp_sum(v0*Wt[lane]     + v1*Wt[lane+32]     + v2*Wt[lane+64]     + v3*Wt[lane+96]);
    float su = warp_sum(v0*Wu[lane]     + v1*Wu[lane+32]     + v2*Wu[lane+64]     + v3*Wu[lane+96]);

    // p0 = tanh(v@Wp + bp): batched butterfly over 16 independent accumulators
    float acc[PQ];
#pragma unroll
    for (int k = 0; k < PQ; k++)
        acc[k] = v0*Wp[lane*PQ+k] + v1*Wp[(lane+32)*PQ+k] +
                 v2*Wp[(lane+64)*PQ+k] + v3*Wp[(lane+96)*PQ+k];
#pragma unroll
    for (int o = 16; o; o >>= 1) {
#pragma unroll
        for (int k = 0; k < PQ; k++) acc[k] += __shfl_xor_sync(0xffffffffu, acc[k], o);
    }
    float pk = 0.f;
#pragma unroll
    for (int k = 0; k < PQ; k++) if (lane == k) pk = ftanh(acc[k] + bp[k]);

    float pd0 = warp_sum(lane < PQ ? pk * Wt[ND+lane] : 0.f);
    float pwu = warp_sum(lane < PQ ? pk * Wu[ND+lane] : 0.f);
    float pn  = warp_sum(lane < PQ ? pk * pk          : 0.f);
    if (lane < PQ) g_p0[n*PQ+lane] = pk;
    if (lane == 0) {
        g_a[n] = sa; g_c[n] = sc; g_avt[n] = st; g_avu[n] = su;
        g_pd0[n] = pd0; g_pwu[n] = pwu; g_pn[n] = pn;
    }
}

// ======== k2: edge weights (thread/edge; dot already hoisted) ========
__global__ void k2(const int* __restrict__ us, const int* __restrict__ vs,
                   const float* __restrict__ be)
{
    int e = blockIdx.x * blockDim.x + threadIdx.x;
    if (e >= Ee) return;
    int u = us[e], v = vs[e];
    float w = fsigmoid(g_a[u] + g_c[v] + g_se[e] + be[0]);
    int s1 = g_slotU[e];
    if (s1 < MAXD) g_wincT[s1 * Nn + u] = w;
    if (u != v) {
        int s2 = g_slotV[e];
        if (s2 < MAXD) g_wincT[s2 * Nn + v] = w;
        atomicAdd(&g_Wn[u], w);
        atomicAdd(&g_Wn[v], w);
    }
}

// ======== k3: q0 = tanh((e@v)@Wq + bq), qd0 (warp/node, butterfly) ========
__global__ void k3(const float* __restrict__ vf, const float* __restrict__ Wq,
                   const float* __restrict__ bq, const float* __restrict__ Wu)
{
    int n    = (blockIdx.x * blockDim.x + threadIdx.x) >> 5;
    int lane = threadIdx.x & 31;
    float x0 = vf[n*ND+lane], x1 = vf[n*ND+lane+32], x2 = vf[n*ND+lane+64], x3 = vf[n*ND+lane+96];
    float Wn = g_Wn[n];
    float e0 = Wn*x0, e1 = Wn*x1, e2 = Wn*x2, e3 = Wn*x3;
    int deg = min(g_cnt[n], MAXD);
    for (int j = 0; j < deg; j++) {
        int   o = g_adjT[j*Nn + n];
        float w = g_wincT[j*Nn + n];
        e0 += w * vf[o*ND+lane];
        e1 += w * vf[o*ND+lane+32];
        e2 += w * vf[o*ND+lane+64];
        e3 += w * vf[o*ND+lane+96];
    }
    float acc[PQ];
#pragma unroll
    for (int k = 0; k < PQ; k++)
        acc[k] = e0*Wq[lane*PQ+k] + e1*Wq[(lane+32)*PQ+k] +
                 e2*Wq[(lane+64)*PQ+k] + e3*Wq[(lane+96)*PQ+k];
#pragma unroll
    for (int o = 16; o; o >>= 1) {
#pragma unroll
        for (int k = 0; k < PQ; k++) acc[k] += __shfl_xor_sync(0xffffffffu, acc[k], o);
    }
    float qk = 0.f;
#pragma unroll
    for (int k = 0; k < PQ; k++) if (lane == k) qk = ftanh(acc[k] + bq[k]);

    float qd0 = warp_sum(lane < PQ ? qk * Wu[ND+lane] : 0.f);
    if (lane < PQ) g_q0[n*PQ+lane] = qk;
    if (lane == 0) g_qd0[n] = qd0;
}

// ======== kBig: zub + 4 layers + outputs; 16 blocks x 256, SMEM adjacency ========
__global__ void __launch_bounds__(GB_BT, 1)
kBig(const float* __restrict__ Wt, const float* __restrict__ Wu, float* __restrict__ out)
{
    extern __shared__ char smraw[];
    float*          s_w = (float*)smraw;                   // [MAXD][GB_BT]
    unsigned short* s_o = (unsigned short*)(s_w + MAXD*GB_BT);
    __shared__ float sh[8];
    __shared__ float shPN;

    const int t = threadIdx.x;
    const int n = blockIdx.x * GB_BT + t;         // thread per node
    const int lane = t & 31;

    float nWt = 0.f, nWu = 0.f, dTU = 0.f;
    float wt2[PQ], wu2[PQ];
#pragma unroll
    for (int k = 0; k < PQ; k++) {
        float a = Wu[ND+k], b = Wt[ND+k];
        wt2[k] = b; wu2[k] = a;
        nWu += a*a; nWt += b*b; dTU += a*b;
    }

    const int   deg = min(g_cnt[n], MAXD);
    const int   mol = g_mol[n];
    const float Wn  = g_Wn[n];
    const float pd0 = g_pd0[n], pwu = g_pwu[n];

    // ---- prologue: cache adjacency in SMEM (own slots only; no sync needed) ----
    for (int j = 0; j < deg; j++) {
        s_o[j*GB_BT + t] = (unsigned short)g_adjT[j*Nn + n];
        s_w[j*GB_BT + t] = g_wincT[j*Nn + n];
    }

    // ---- P0: zub gather + layer-1 locals ----
    float s = Wn * g_qd0[n];
    for (int j = 0; j < deg; j++)
        s += s_w[j*GB_BT + t] * g_qd0[s_o[j*GB_BT + t]];
    const float zub = g_avu[n] + s;
    const float atp = g_avt[n] + pd0;

    float st = fsigmoid(atp), su = fsigmoid(zub);
    float cum = st;
    g_scA[n] = make_float2(su, cum);
    float wS = 4.f * st, wG = 0.f, cumG = 0.f;
    atomicAdd(&g_Sm[mol], st);
    {
        float sl = st*st*nWt - 2.f*st*pd0;
        sl = warp_sum(sl);
        if (lane == 0) atomicAdd(&g_S[0], sl);
    }
    gsync();  // 1

    // ---- P1..P4 ----
    for (int ph = 1; ph <= 4; ph++) {
        const float2* IN  = (ph & 1) ? g_scA : g_scB;
        float2*       OUT = (ph & 1) ? g_scB : g_scA;

        float gg = Wn * su, G = Wn * cum;
        for (int j = 0; j < deg; j++) {
            float  w  = s_w[j*GB_BT + t];
            float2 sc = IN[s_o[j*GB_BT + t]];
            gg += w * sc.x;
            G  += w * sc.y;
        }
        atomicAdd(&g_Gm[(ph-1)*Mm + mol], gg);
        cumG += gg;
        wG += (float)((ph == 1) ? 4 : (5 - ph)) * gg;

        if (ph < 4) {
            float zt = atp - TAU * (dTU * cumG + FRIC * nWt * cum);
            float stn = fsigmoid(zt);
            float zu = zub + TAU * dTU * G;
            float sun = fsigmoid(zu);
            float cumn = cum + stn;
            OUT[n] = make_float2(sun, cumn);
            wS += (float)(4 - ph) * stn;
            atomicAdd(&g_Sm[ph*Mm + mol], stn);
            float alpha = stn + TAU * FRIC * cum;
            float beta  = TAU * cumG;
            float sl = alpha*alpha*nWt + beta*beta*nWu + 2.f*alpha*beta*dTU
                     - 2.f*alpha*pd0 - 2.f*beta*pwu;
            sl = warp_sum(sl);
            if (lane == 0) atomicAdd(&g_S[ph], sl);
            if (ph == 3) {   // zt/zu/stn are layer-4 values
                atomicAdd(&g_h[mol], fsoftplus(zt) + fsoftplus(zu));
                atomicAdd(&g_d[mol], stn * stn);
            }
            su = sun; cum = cumn;
        }
        gsync();  // 2..5
    }

    // ---- outputs: thread n writes its 16 p and 16 q values ----
    {
        float cp1 = -(TAU*FRIC) * wS, cp2 = -TAU * wG, cq = TAU * wS;
#pragma unroll
        for (int k = 0; k < PQ; k++) {
            out[n*PQ + k]      = 0.2f * (5.f*g_p0[n*PQ+k] + cp1*wt2[k] + cp2*wu2[k]);
            out[NP + n*PQ + k] = 0.2f * (5.f*g_q0[n*PQ+k] + cq*wt2[k]);
        }
    }
    g_cnt[n] = 0;

    // ---- block 0: scalars + h/d ----
    if (blockIdx.x == 0) {
        float pn = 0.f;
        for (int i = t; i < Nn; i += GB_BT) pn += g_pn[i];
        pn = warp_sum(pn);
        if (lane == 0) sh[t >> 5] = pn;
        __syncthreads();
        if (t == 0) {
            float s0 = 0.f;
            for (int i = 0; i < 8; i++) s0 += sh[i];
            shPN = s0;
        }
        __syncthreads();
        if (t < 32) {
            float cT = 0.f;
            for (int i = 0; i < LAYERS; i++) {
                float term = 0.f;
                for (int m = lane; m < Mm; m += 32) {
                    float Gm = g_Gm[i*Mm+m], Sm = g_Sm[i*Mm+m];
                    term += Gm*Gm*nWu + 2.f*FRIC*Gm*Sm*dTU + FRIC*FRIC*Sm*Sm*nWt;
                }
                term = warp_sum(term);
                cT += TAU * sqrtf(term);
            }
            if (lane == 0) {
                float sT = 0.f;
                for (int i = 0; i < LAYERS; i++) sT += sqrtf(g_S[i] + shPN);
                out[2*NP + 0] = sT;
                out[2*NP + 1] = cT;
            }
        }
        if (t < Mm) {
            out[2*NP + 2 + t]      = g_h[t];
            out[2*NP + 2 + Mm + t] = g_d[t] * nWt;
        }
    }
}

extern "C" void kernel_launch(void* const* d_in, const int* in_sizes, int n_in,
                              void* d_out, int out_size)
{
    const float* vf  = (const float*)d_in[0];
    const float* ef  = (const float*)d_in[1];
    const int*   us  = (const int*)  d_in[2];
    const int*   vs  = (const int*)  d_in[3];
    const float* mnm = (const float*)d_in[4];
    const float* We  = (const float*)d_in[8];
    const float* be  = (const float*)d_in[9];
    const float* Wp  = (const float*)d_in[10];
    const float* bp  = (const float*)d_in[11];
    const float* Wq  = (const float*)d_in[12];
    const float* bq  = (const float*)d_in[13];
    const float* Wt  = (const float*)d_in[14];
    const float* Wu  = (const float*)d_in[15];
    float* out = (float*)d_out;

    cudaFuncSetAttribute(kBig, cudaFuncAttributeMaxDynamicSharedMemorySize, DYN_SMEM);

    k1<<<512, 256>>>(vf, ef, mnm, us, vs, We, Wp, bp, Wt, Wu);
    k2<<<32, 256>>>(us, vs, be);
    k3<<<512, 256>>>(vf, Wq, bq, Wu);
    kBig<<<GB_NB, GB_BT, DYN_SMEM>>>(Wt, Wu, out);
}

// round 14
// speedup vs baseline: 1.2396x; 1.1528x over previous
#include <cuda_runtime.h>
#include <math.h>

#define Nn 4096
#define Ee 8192
#define Mm 128
#define ND 128
#define ED 64
#define PQ 16
#define NP (Nn*PQ)
#define LAYERS 4
#define TAU 0.25f
#define FRIC 0.1f
#define MAXD 32
#define GB_NB 64
#define GB_BT 64

// ---------------- device scratch (no allocation allowed) ----------------
__device__ float g_a[Nn], g_c[Nn], g_avt[Nn], g_avu[Nn];
__device__ float g_pd0[Nn], g_pwu[Nn], g_pn[Nn], g_qd0[Nn], g_Wn[Nn];
__device__ int   g_mol[Nn];
__device__ int   g_cnt[Nn];            // zero at k1 entry; reset in kBig
__device__ int   g_adjT[MAXD * Nn];    // [slot][node] -> other-node id (coalesced)
__device__ float g_wincT[MAXD * Nn];   // [slot][node] -> edge weight
__device__ int   g_slotU[Ee], g_slotV[Ee];
__device__ float g_p0[NP], g_q0[NP];
__device__ float2 g_scA[Nn], g_scB[Nn];   // packed (su, cumSt)
__device__ float g_Gm[LAYERS*Mm], g_Sm[LAYERS*Mm], g_h[Mm], g_d[Mm], g_S[LAYERS];
__device__ unsigned g_bar;             // monotonic grid-barrier counter

__device__ __forceinline__ float warp_sum(float v) {
#pragma unroll
    for (int o = 16; o; o >>= 1) v += __shfl_xor_sync(0xffffffffu, v, o);
    return v;
}
__device__ __forceinline__ float sigmoidf(float x) { return 1.f / (1.f + expf(-x)); }
__device__ __forceinline__ float fsigmoid(float x) { return 1.f / (1.f + __expf(-x)); }
__device__ __forceinline__ float fsoftplus(float x) { return fmaxf(x, 0.f) + __logf(1.f + __expf(-fabsf(x))); }

// grid barrier across GB_NB blocks; monotonic counter, busy-spin (no nanosleep
// wakeup quantization). Each launch consumes exactly 5*GB_NB increments.
__device__ __forceinline__ void gsync() {
    __threadfence();
    __syncthreads();
    if (threadIdx.x == 0) {
        unsigned t = atomicAdd(&g_bar, 1u);
        unsigned target = (t / GB_NB + 1u) * GB_NB;
        while (*((volatile unsigned*)&g_bar) < target) { }
    }
    __syncthreads();
    __threadfence();
}
// arrive-only (final barrier for blocks that have no cross-block reads left)
__device__ __forceinline__ void garrive() {
    __threadfence();
    __syncthreads();
    if (threadIdx.x == 0) atomicAdd(&g_bar, 1u);
}

// ======== k1: node setup (warp/node) + mol ids + adjacency + accumulator zeroing ========
__global__ void k1(const float* __restrict__ vf, const float* __restrict__ mnm,
                   const int* __restrict__ us, const int* __restrict__ vs,
                   const float* __restrict__ We, const float* __restrict__ Wp,
                   const float* __restrict__ bp, const float* __restrict__ Wt,
                   const float* __restrict__ Wu)
{
    int tid  = blockIdx.x * blockDim.x + threadIdx.x;   // 131072 threads
    int lane = threadIdx.x & 31;
    int n    = tid >> 5;                                 // warp -> node

    if (tid < Nn) g_Wn[tid] = 0.f;
    if (tid < LAYERS*Mm) { g_Gm[tid] = 0.f; g_Sm[tid] = 0.f; }
    if (tid < Mm) { g_h[tid] = 0.f; g_d[tid] = 0.f; }
    if (tid < LAYERS) g_S[tid] = 0.f;

    for (int idx = tid; idx < Mm * Nn; idx += 131072)
        if (mnm[idx] > 0.5f) g_mol[idx & (Nn - 1)] = idx >> 12;

    for (int e = tid; e < Ee; e += 131072) {
        int u = us[e], v = vs[e];
        int s1 = atomicAdd(&g_cnt[u], 1);
        if (s1 < MAXD) g_adjT[s1 * Nn + u] = v;
        g_slotU[e] = s1;
        if (u != v) {
            int s2 = atomicAdd(&g_cnt[v], 1);
            if (s2 < MAXD) g_adjT[s2 * Nn + v] = u;
            g_slotV[e] = s2;
        }
    }

    float v0 = vf[n*ND+lane], v1 = vf[n*ND+lane+32], v2 = vf[n*ND+lane+64], v3 = vf[n*ND+lane+96];
    float sa = warp_sum(v0*We[lane]     + v1*We[lane+32]     + v2*We[lane+64]     + v3*We[lane+96]);
    float sc = warp_sum(v0*We[192+lane] + v1*We[192+lane+32] + v2*We[192+lane+64] + v3*We[192+lane+96]);
    float st = warp_sum(v0*Wt[lane]     + v1*Wt[lane+32]     + v2*Wt[lane+64]     + v3*Wt[lane+96]);
    float su = warp_sum(v0*Wu[lane]     + v1*Wu[lane+32]     + v2*Wu[lane+64]     + v3*Wu[lane+96]);

    float pk = 0.f;
#pragma unroll
    for (int k = 0; k < PQ; k++) {
        float s = warp_sum(v0*Wp[lane*PQ+k] + v1*Wp[(lane+32)*PQ+k] +
                           v2*Wp[(lane+64)*PQ+k] + v3*Wp[(lane+96)*PQ+k]);
        if (lane == k) pk = tanhf(s + bp[k]);
    }
    float pd0 = warp_sum(lane < PQ ? pk * Wt[ND+lane] : 0.f);
    float pwu = warp_sum(lane < PQ ? pk * Wu[ND+lane] : 0.f);
    float pn  = warp_sum(lane < PQ ? pk * pk          : 0.f);
    if (lane < PQ) g_p0[n*PQ+lane] = pk;
    if (lane == 0) {
        g_a[n] = sa; g_c[n] = sc; g_avt[n] = st; g_avu[n] = su;
        g_pd0[n] = pd0; g_pwu[n] = pwu; g_pn[n] = pn;
    }
}

// ======== k2: edge weights (warp/edge) ========
__global__ void k2(const float* __restrict__ ef,
                   const int* __restrict__ us, const int* __restrict__ vs,
                   const float* __restrict__ We, const float* __restrict__ be)
{
    int e    = (blockIdx.x * blockDim.x + threadIdx.x) >> 5;
    int lane = threadIdx.x & 31;
    if (e >= Ee) return;
    float s = ef[e*ED+lane] * We[128+lane] + ef[e*ED+32+lane] * We[160+lane];
    s = warp_sum(s);
    if (lane == 0) {
        int u = us[e], v = vs[e];
        float w = sigmoidf(g_a[u] + g_c[v] + s + be[0]);
        int s1 = g_slotU[e];
        if (s1 < MAXD) g_wincT[s1 * Nn + u] = w;
        if (u != v) {
            int s2 = g_slotV[e];
            if (s2 < MAXD) g_wincT[s2 * Nn + v] = w;
            atomicAdd(&g_Wn[u], w);
            atomicAdd(&g_Wn[v], w);
        }
    }
}

// ======== k3: q0 = tanh((e@v)@Wq + bq), qd0 (warp/node) ========
__global__ void k3(const float* __restrict__ vf, const float* __restrict__ Wq,
                   const float* __restrict__ bq, const float* __restrict__ Wu)
{
    int n    = (blockIdx.x * blockDim.x + threadIdx.x) >> 5;
    int lane = threadIdx.x & 31;
    float x0 = vf[n*ND+lane], x1 = vf[n*ND+lane+32], x2 = vf[n*ND+lane+64], x3 = vf[n*ND+lane+96];
    float Wn = g_Wn[n];
    float e0 = Wn*x0, e1 = Wn*x1, e2 = Wn*x2, e3 = Wn*x3;
    int deg = min(g_cnt[n], MAXD);
    for (int j = 0; j < deg; j++) {
        int   o = g_adjT[j*Nn + n];
        float w = g_wincT[j*Nn + n];
        e0 += w * vf[o*ND+lane];
        e1 += w * vf[o*ND+lane+32];
        e2 += w * vf[o*ND+lane+64];
        e3 += w * vf[o*ND+lane+96];
    }
    float qk = 0.f;
#pragma unroll
    for (int k = 0; k < PQ; k++) {
        float s = warp_sum(e0*Wq[lane*PQ+k] + e1*Wq[(lane+32)*PQ+k] +
                           e2*Wq[(lane+64)*PQ+k] + e3*Wq[(lane+96)*PQ+k]);
        if (lane == k) qk = tanhf(s + bq[k]);
    }
    float qd0 = warp_sum(lane < PQ ? qk * Wu[ND+lane] : 0.f);
    if (lane < PQ) g_q0[n*PQ+lane] = qk;
    if (lane == 0) g_qd0[n] = qd0;
}

// ======== kBig: zub + 4 layers + outputs; 64 blocks x 64 threads ========
__global__ void __launch_bounds__(GB_BT, 1)
kBig(const float* __restrict__ Wt, const float* __restrict__ Wu, float* __restrict__ out)
{
    __shared__ unsigned short s_o[MAXD * GB_BT];  // 4 KB
    __shared__ float          s_w[MAXD * GB_BT];  // 8 KB
    __shared__ float sh[2];
    __shared__ float shPN;

    const int t = threadIdx.x;
    const int n = blockIdx.x * GB_BT + t;         // thread per node
    const int lane = t & 31;

    float nWt = 0.f, nWu = 0.f, dTU = 0.f;
    float wt2[PQ], wu2[PQ];
#pragma unroll
    for (int k = 0; k < PQ; k++) {
        float a = Wu[ND+k], b = Wt[ND+k];
        wt2[k] = b; wu2[k] = a;
        nWu += a*a; nWt += b*b; dTU += a*b;
    }

    const int   deg = min(g_cnt[n], MAXD);
    const int   mol = g_mol[n];
    const float Wn  = g_Wn[n];
    const float pd0 = g_pd0[n], pwu = g_pwu[n];

    // ---- prologue: cache adjacency in SMEM (own slots only; no sync needed) ----
    for (int j = 0; j < deg; j++) {
        s_o[j*GB_BT + t] = (unsigned short)g_adjT[j*Nn + n];
        s_w[j*GB_BT + t] = g_wincT[j*Nn + n];
    }

    // ---- P0: zub gather + layer-1 locals ----
    float s = Wn * g_qd0[n];
    for (int j = 0; j < deg; j++)
        s += s_w[j*GB_BT + t] * g_qd0[s_o[j*GB_BT + t]];
    const float zub = g_avu[n] + s;
    const float atp = g_avt[n] + pd0;

    float st = fsigmoid(atp), su = fsigmoid(zub);
    float cum = st;
    g_scA[n] = make_float2(su, cum);
    float wS = 4.f * st, wG = 0.f, cumG = 0.f;
    atomicAdd(&g_Sm[mol], st);
    {
        float sl = st*st*nWt - 2.f*st*pd0;
        sl = warp_sum(sl);
        if (lane == 0) atomicAdd(&g_S[0], sl);
    }
    gsync();  // 1

    // ---- P1..P4 ----
    for (int ph = 1; ph <= 4; ph++) {
        const float2* IN  = (ph & 1) ? g_scA : g_scB;
        float2*       OUT = (ph & 1) ? g_scB : g_scA;

        float gg = Wn * su, G = Wn * cum;
        for (int j = 0; j < deg; j++) {
            float  w  = s_w[j*GB_BT + t];
            float2 sc = IN[s_o[j*GB_BT + t]];
            gg += w * sc.x;
            G  += w * sc.y;
        }
        atomicAdd(&g_Gm[(ph-1)*Mm + mol], gg);
        cumG += gg;
        wG += (float)((ph == 1) ? 4 : (5 - ph)) * gg;

        if (ph < 4) {
            float zt = atp - TAU * (dTU * cumG + FRIC * nWt * cum);
            float stn = fsigmoid(zt);
            float zu = zub + TAU * dTU * G;
            float sun = fsigmoid(zu);
            float cumn = cum + stn;
            OUT[n] = make_float2(sun, cumn);
            wS += (float)(4 - ph) * stn;
            atomicAdd(&g_Sm[ph*Mm + mol], stn);
            float alpha = stn + TAU * FRIC * cum;
            float beta  = TAU * cumG;
            float sl = alpha*alpha*nWt + beta*beta*nWu + 2.f*alpha*beta*dTU
                     - 2.f*alpha*pd0 - 2.f*beta*pwu;
            sl = warp_sum(sl);
            if (lane == 0) atomicAdd(&g_S[ph], sl);
            if (ph == 3) {   // zt/zu/stn are layer-4 values
                atomicAdd(&g_h[mol], fsoftplus(zt) + fsoftplus(zu));
                atomicAdd(&g_d[mol], stn * stn);
            }
            su = sun; cum = cumn;
        }
        if (ph < 4) gsync();                       // 2..4
        else if (blockIdx.x == 0) gsync();         // 5: only block 0 must WAIT
        else garrive();                            //    others just arrive
    }

    // ---- outputs: thread n writes its 16 p and 16 q values (thread-local state) ----
    {
        float cp1 = -(TAU*FRIC) * wS, cp2 = -TAU * wG, cq = TAU * wS;
#pragma unroll
        for (int k = 0; k < PQ; k++) {
            out[n*PQ + k]      = 0.2f * (5.f*g_p0[n*PQ+k] + cp1*wt2[k] + cp2*wu2[k]);
            out[NP + n*PQ + k] = 0.2f * (5.f*g_q0[n*PQ+k] + cq*wt2[k]);
        }
    }
    g_cnt[n] = 0;

    // ---- block 0: scalars + h/d (waited at barrier 5, so all atomics visible) ----
    if (blockIdx.x == 0) {
        float pn = 0.f;
        for (int i = t; i < Nn; i += GB_BT) pn += g_pn[i];
        pn = warp_sum(pn);
        if (lane == 0) sh[t >> 5] = pn;
        __syncthreads();
        if (t == 0) shPN = sh[0] + sh[1];
        __syncthreads();
        if (t < 32) {
            float cT = 0.f;
            for (int i = 0; i < LAYERS; i++) {
                float term = 0.f;
                for (int m = lane; m < Mm; m += 32) {
                    float Gm = g_Gm[i*Mm+m], Sm = g_Sm[i*Mm+m];
                    term += Gm*Gm*nWu + 2.f*FRIC*Gm*Sm*dTU + FRIC*FRIC*Sm*Sm*nWt;
                }
                term = warp_sum(term);
                cT += TAU * sqrtf(term);
            }
            if (lane == 0) {
                float sT = 0.f;
                for (int i = 0; i < LAYERS; i++) sT += sqrtf(g_S[i] + shPN);
                out[2*NP + 0] = sT;
                out[2*NP + 1] = cT;
            }
        }
        for (int m = t; m < Mm; m += GB_BT) {
            out[2*NP + 2 + m]      = g_h[m];
            out[2*NP + 2 + Mm + m] = g_d[m] * nWt;
        }
    }
}

extern "C" void kernel_launch(void* const* d_in, const int* in_sizes, int n_in,
                              void* d_out, int out_size)
{
    const float* vf  = (const float*)d_in[0];
    const float* ef  = (const float*)d_in[1];
    const int*   us  = (const int*)  d_in[2];
    const int*   vs  = (const int*)  d_in[3];
    const float* mnm = (const float*)d_in[4];
    const float* We  = (const float*)d_in[8];
    const float* be  = (const float*)d_in[9];
    const float* Wp  = (const float*)d_in[10];
    const float* bp  = (const float*)d_in[11];
    const float* Wq  = (const float*)d_in[12];
    const float* bq  = (const float*)d_in[13];
    const float* Wt  = (const float*)d_in[14];
    const float* Wu  = (const float*)d_in[15];
    float* out = (float*)d_out;

    k1<<<512, 256>>>(vf, mnm, us, vs, We, Wp, bp, Wt, Wu);
    k2<<<1024, 256>>>(ef, us, vs, We, be);
    k3<<<512, 256>>>(vf, Wq, bq, Wu);
    kBig<<<GB_NB, GB_BT>>>(Wt, Wu, out);
}